// round 12
// baseline (speedup 1.0000x reference)
#include <cuda_runtime.h>

#define NTHREADS 416   // 13 warps: warps 0-5 im0, warp 6 split, warps 7-12 im1

typedef unsigned long long u64;

__device__ __forceinline__ u64 mul2(u64 a, u64 b) {
    u64 d; asm("mul.rn.f32x2 %0,%1,%2;" : "=l"(d) : "l"(a), "l"(b)); return d;
}
__device__ __forceinline__ u64 add2(u64 a, u64 b) {
    u64 d; asm("add.rn.f32x2 %0,%1,%2;" : "=l"(d) : "l"(a), "l"(b)); return d;
}
__device__ __forceinline__ u64 fma2(u64 a, u64 b, u64 c) {
    u64 d; asm("fma.rn.f32x2 %0,%1,%2,%3;" : "=l"(d) : "l"(a), "l"(b), "l"(c)); return d;
}
__device__ __forceinline__ u64 pk2(float lo, float hi) {
    u64 d; asm("mov.b64 %0,{%1,%2};" : "=l"(d) : "f"(lo), "f"(hi)); return d;
}
__device__ __forceinline__ void upk(u64 v, float& lo, float& hi) {
    asm("mov.b64 {%0,%1},%2;" : "=f"(lo), "=f"(hi) : "l"(v));
}
__device__ __forceinline__ u64 neg1pk() {
    u64 d; asm("mov.b64 %0,0xBF800000BF800000;" : "=l"(d)); return d;
}

// Packed Ry stage on pack-index bit kb for wire w; constants from smem per-stage.
#define RYWP(kb, w) { \
    const u64 cv = cP[w], sv = sP[w], nsv = nsP[w]; \
    _Pragma("unroll") \
    for (int k = 0; k < 8; k++) { \
        if (!(k & (kb))) { \
            u64 a0 = P[k], a1 = P[k | (kb)]; \
            P[k]        = fma2(nsv, a1, mul2(cv, a0)); \
            P[k | (kb)] = fma2(cv,  a1, mul2(sv, a0)); \
        } \
    } }

__global__ __launch_bounds__(NTHREADS, 4)
void quanv_kernel(const float* __restrict__ x,
                  const float* __restrict__ params,
                  const float* __restrict__ W,
                  const float* __restrict__ bias,
                  float* __restrict__ out)
{
    __shared__ float p0s[4];
    __shared__ u64  cP[4], sP[4], nsP[4];    // packed (c,c),(s,s),(-s,-s) wires 0,1,3
    __shared__ u64  csa_s, csb_s;            // wire-2 fold: (c2,s2), (-s2,c2)
    __shared__ float wsum[26][10];           // one row per HALF-warp

    const int b = blockIdx.x;                // image pair
    const int t = threadIdx.x;
    const int wid = t >> 5;
    const int lane = t & 31;

    if (t < 4) {
        p0s[t] = params[t];
        float sv, cv;
        __sincosf(params[4 + t] * 0.5f, &sv, &cv);
        if (t == 2) { csa_s = pk2(cv, sv); csb_s = pk2(-sv, cv); }
        else        { cP[t] = pk2(cv, cv); sP[t] = pk2(sv, sv); nsP[t] = pk2(-sv, -sv); }
    }
    __syncthreads();

    // Thread -> (image, patch) map. warps 0-5: im0 p=wid*32+lane;
    // warp 6: lanes 0-3 -> im0 p=192+, lanes 16-19 -> im1 p=192+;
    // warps 7-12: im1 p=(wid-7)*32+lane.
    int im, p;
    bool active;
    if (wid < 6)      { im = 0; p = wid * 32 + lane;        active = true; }
    else if (wid == 6){ im = lane >> 4; p = 192 + (lane & 15); active = (lane & 15) < 4; }
    else              { im = 1; p = (wid - 7) * 32 + lane;  active = true; }

    float vals[16];
    #pragma unroll
    for (int c = 0; c < 16; c++) vals[c] = 0.0f;

    if (active) {
        const int pr = p / 14, pc = p % 14;
        // Direct, near-coalesced patch gather from global.
        const float* px = x + (2 * b + im) * 784 + pr * 56 + pc * 2;
        const float2 r0 = *reinterpret_cast<const float2*>(px);
        const float2 r1 = *reinterpret_cast<const float2*>(px + 28);

        float cc[4], ss[4];
        __sincosf((r0.x + p0s[0]) * 0.5f, &ss[0], &cc[0]);
        __sincosf((r0.y + p0s[1]) * 0.5f, &ss[1], &cc[1]);
        __sincosf((r1.x + p0s[2]) * 0.5f, &ss[2], &cc[2]);
        __sincosf((r1.y + p0s[3]) * 0.5f, &ss[3], &cc[3]);

        const u64 C0 = pk2(cc[0], cc[0]), S0 = pk2(ss[0], ss[0]);
        const u64 C1 = pk2(cc[1], cc[1]), S1 = pk2(ss[1], ss[1]);
        const u64 C2 = pk2(cc[2], cc[2]), S2 = pk2(ss[2], ss[2]);
        const u64 C3 = pk2(cc[3], cc[3]), S3 = pk2(ss[3], ss[3]);

        // a23 table (dup-packed) with layer-1 Ry(wire2) folded in.
        u64 D23[4];
        D23[0] = mul2(C2, C3); D23[1] = mul2(C2, S3);
        D23[2] = mul2(S2, C3); D23[3] = mul2(S2, S3);
        const u64 csa = csa_s, csb = csb_s;
        u64 B23[4];
        #pragma unroll
        for (int y = 0; y < 4; y++)
            B23[y] = fma2(csa, D23[y], mul2(csb, D23[y ^ 3]));

        u64 A01[4];
        A01[0] = mul2(C0, C1); A01[1] = mul2(C0, S1);
        A01[2] = mul2(S0, C1); A01[3] = mul2(S0, S1);

        // Product state, layer-0 CNOTs folded (label permutation), pack lane = q2.
        u64 P[8];
        #pragma unroll
        for (int k = 0; k < 8; k++) {
            const int u0 = (k >> 2) & 1, u1 = (k >> 1) & 1, u3 = k & 1;
            const int xa = ((u0 ^ u3) << 1) | (u0 ^ u1 ^ u3);
            const int y  = (u1 << 1) | u3;
            P[k] = mul2(A01[xa], B23[y]);
        }

        RYWP(4, 0);
        RYWP(2, 1);
        RYWP(1, 3);

        // Measurement, layer-1 CNOTs folded into sign masks.
        const u64 NEG1 = neg1pk();
        #define SUB2(a, bb) fma2((bb), NEG1, (a))

        u64 Q[8];
        #pragma unroll
        for (int k = 0; k < 8; k++) Q[k] = mul2(P[k], P[k]);

        u64 Sp[4], Sm[4];
        #pragma unroll
        for (int j = 0; j < 4; j++) { Sp[j] = add2(Q[j], Q[j+4]); Sm[j] = SUB2(Q[j], Q[j+4]); }

        u64 z0p = SUB2(SUB2(Sp[0], Sp[1]), SUB2(Sp[2], Sp[3]));
        u64 z1p = SUB2(add2(Sm[0], Sm[1]), add2(Sm[2], Sm[3]));
        u64 z3p = SUB2(SUB2(Sm[0], Sm[1]), SUB2(Sm[2], Sm[3]));

        float l0, h0, l1, h1, l3, h3;
        upk(z0p, l0, h0); upk(z1p, l1, h1); upk(z3p, l3, h3);
        const float z0 = l0 - h0;
        const float z1 = l1 + h1;
        const float z2 = l1 - h1;
        const float z3 = l3 - h3;

        // Per-patch linear partials, coalesced row-major W.
        const u64 z01 = pk2(z0, z1), z23 = pk2(z2, z3);
        #pragma unroll
        for (int c = 0; c < 10; c++) {
            u64 w01, w23;
            asm("ld.global.nc.v2.b64 {%0,%1},[%2];"
                : "=l"(w01), "=l"(w23)
                : "l"(W + c * 784 + 4 * p));
            u64 acc = fma2(z23, w23, mul2(z01, w01));
            float alo, ahi; upk(acc, alo, ahi);
            vals[c] = alo + ahi;
        }
        #undef SUB2
    }

    // Split-butterfly over each 16-lane half (masks 1,2,4,8 never cross halves).
    #pragma unroll
    for (int stage = 0; stage < 4; stage++) {
        const int m = 1 << stage;
        const int h = 8 >> stage;
        const bool hi = (lane & m) != 0;
        #pragma unroll
        for (int c = 0; c < h; c++) {
            float send = hi ? vals[c]     : vals[c + h];
            float keep = hi ? vals[c + h] : vals[c];
            vals[c] = keep + __shfl_xor_sync(0xffffffffu, send, m);
        }
    }
    // No xor16: each half-warp writes its own row.
    const int cls = __brev(lane & 15) >> 28;   // bitrev4
    if (cls < 10) wsum[wid * 2 + (lane >> 4)][cls] = vals[0];
    __syncthreads();

    // Warp 0: combine rows + log_softmax for both images.
    // im0 rows [0,13) (warps 0-5 halves + warp6-lo); im1 rows [13,26).
    if (t < 32) {
        const int imo = t >> 4, c = t & 15;
        float logit = 0.0f, e = 0.0f;
        if (c < 10) {
            float v = bias[c];
            const int r0 = imo * 13;
            #pragma unroll
            for (int r = 0; r < 13; r++) v += wsum[r0 + r][c];
            logit = v;
            e = __expf(v);   // logits are tiny; no max-shift needed
        }
        #pragma unroll
        for (int off = 8; off > 0; off >>= 1)
            e += __shfl_xor_sync(0xffffffffu, e, off);
        if (c < 10) out[(2 * b + imo) * 10 + c] = logit - __logf(e);
    }
}

extern "C" void kernel_launch(void* const* d_in, const int* in_sizes, int n_in,
                              void* d_out, int out_size) {
    const float* x      = (const float*)d_in[0];   // [8192, 28, 28]
    const float* params = (const float*)d_in[1];   // [2, 4]
    const float* W      = (const float*)d_in[2];   // [10, 784]
    const float* bias   = (const float*)d_in[3];   // [10]
    float* out          = (float*)d_out;           // [8192, 10]

    const int B = in_sizes[0] / 784;
    quanv_kernel<<<B / 2, NTHREADS>>>(x, params, W, bias, out);
}